// round 16
// baseline (speedup 1.0000x reference)
#include <cuda_runtime.h>

#define NB 512
#define NT 1024
#define NK 48
#define SSTART 46
#define SEND 47
#define NEGV (-10000.0f)
#define L2E 1.4426950408889634f
#define LN2F 0.6931471805599453f

// per-batch slot: bp[NT*NK] u8 | v0[NK] | v1[NK] | e0[NK] | e1[NK] (each padded)
#define SLOT_V0 (NT*NK)
#define SLOT_V1 (SLOT_V0 + 256)
#define SLOT_E0 (SLOT_V1 + 256)
#define SLOT_E1 (SLOT_E0 + 256)
#define SLOT    (SLOT_E1 + 256)
#define TT_OFF  (4*SLOT)                     // masked trans table (shared by batches)
#define SMEM_BYTES (TT_OFF + NK*NK*4)        // ~209.9KB -> 1 CTA/SM

__device__ __forceinline__ float ex2f(float x){ float y; asm("ex2.approx.ftz.f32 %0, %1;":"=f"(y):"f"(x)); return y; }
__device__ __forceinline__ float lg2f(float x){ float y; asm("lg2.approx.f32 %0, %1;":"=f"(y):"f"(x)); return y; }
__device__ __forceinline__ unsigned long long ffma2(unsigned long long a, unsigned long long b, unsigned long long c){
    unsigned long long d; asm("fma.rn.f32x2 %0, %1, %2, %3;" : "=l"(d) : "l"(a), "l"(b), "l"(c)); return d;
}
__device__ __forceinline__ unsigned long long fadd2(unsigned long long a, unsigned long long b){
    unsigned long long d; asm("add.rn.f32x2 %0, %1, %2;" : "=l"(d) : "l"(a), "l"(b)); return d;
}
__device__ __forceinline__ unsigned long long pk2(float lo, float hi){
    unsigned long long d; asm("mov.b64 %0, {%1, %2};" : "=l"(d) : "f"(lo), "f"(hi)); return d;
}
__device__ __forceinline__ void upk2(unsigned long long v, float& lo, float& hi){
    asm("mov.b64 {%0, %1}, %2;" : "=f"(lo), "=f"(hi) : "l"(v));
}

// R13-proven coarse argmax over 12 groups (48 prevs): exact group max via FMNMX,
// strict > keeps earliest group; in-group index recovered OFF the critical path
// via bit-identical FADD recomputation from smem, first-equal -> exact first-max.
#define VIT_FULL(tp, jj, bm, bi) do { \
    bm = -3.4e38f; int g4 = 0; \
    _Pragma("unroll") \
    for (int c=0;c<12;++c){ \
        unsigned long long y01=fadd2(vv[c].x,(tp)[2*c]); \
        unsigned long long y23=fadd2(vv[c].y,(tp)[2*c+1]); \
        float y0,y1,y2,y3; upk2(y01,y0,y1); upk2(y23,y2,y3); \
        float mg = fmaxf(fmaxf(y0,y1), fmaxf(y2,y3)); \
        if (mg > bm) { bm = mg; g4 = c; } \
    } \
    const int p0 = 4*g4; \
    const float* trow = tT + (jj)*NK + p0; \
    float r0 = vcur[p0  ] + trow[0]; \
    float r1 = vcur[p0+1] + trow[1]; \
    float r2 = vcur[p0+2] + trow[2]; \
    bi = (r0==bm) ? p0 : (r1==bm) ? (p0+1) : (r2==bm) ? (p0+2) : (p0+3); \
} while(0)

// half scan: 6 groups (24 prevs starting at group base6), same exact semantics
#define VIT_HALF(tp, jj, base6, bm, bi) do { \
    bm = -3.4e38f; int g4 = 0; \
    _Pragma("unroll") \
    for (int c=0;c<6;++c){ \
        unsigned long long y01=fadd2(vv[(base6)+c].x,(tp)[2*c]); \
        unsigned long long y23=fadd2(vv[(base6)+c].y,(tp)[2*c+1]); \
        float y0,y1,y2,y3; upk2(y01,y0,y1); upk2(y23,y2,y3); \
        float mg = fmaxf(fmaxf(y0,y1), fmaxf(y2,y3)); \
        if (mg > bm) { bm = mg; g4 = c; } \
    } \
    const int p0 = 4*((base6)+g4); \
    const float* trow = tT + (jj)*NK + p0; \
    float r0 = vcur[p0  ] + trow[0]; \
    float r1 = vcur[p0+1] + trow[1]; \
    float r2 = vcur[p0+2] + trow[2]; \
    bi = (r0==bm) ? p0 : (r1==bm) ? (p0+1) : (r2==bm) ? (p0+2) : (p0+3); \
} while(0)

__global__ __launch_bounds__(256, 1)
void crf_kernel(const float* __restrict__ feats,
                const float* __restrict__ trans,
                float* __restrict__ out)
{
    extern __shared__ char smc[];
    const int tid  = threadIdx.x;
    const int wid  = tid >> 5;
    const int lane = tid & 31;
    const int q    = wid & 3;                        // batch within CTA
    const bool isV = ((wid & 1) == (wid >> 2));      // SMSP gets 1 vit + 1 fwd
    const int b = blockIdx.x * 4 + q;
    char* sb = smc + q * SLOT;
    unsigned char* bp = (unsigned char*)sb;
    float* vS[2] = { (float*)(sb + SLOT_V0), (float*)(sb + SLOT_V1) };
    float* eS[2] = { (float*)(sb + SLOT_E0), (float*)(sb + SLOT_E1) };
    float* tT = (float*)(smc + TT_OFF);              // masked trans table (plain)
    const float* f = feats + (size_t)b * NT * NK;

    // cooperative fill of the masked trans table (one-time)
    for (int idx = tid; idx < NK*NK; idx += 256) {
        const int r = idx / NK, cpos = idx % NK;
        float tv = trans[idx];
        if (r == SSTART) tv = NEGV;                  // no transition into START row
        if (cpos == SEND) tv = NEGV;                 // no transition out of END col
        tT[idx] = tv;
    }

    if (isV) {
        // ============== VITERBI warp: 32 lanes, rebalanced =====================
        // state `lane` (0..31): full scan by this lane.
        // state 32+h (h=lane&15): half scans by lanes h (prevs 0-23) and h+16 (24-47).
        const int h    = lane & 15;
        const int jh   = 32 + h;
        const int base6 = (lane >= 16) ? 6 : 0;

        unsigned long long tpF[NK/2];                // full row, state=lane
        unsigned long long tpH[12];                  // half row, state=jh
        #pragma unroll
        for (int c = 0; c < NK/2; ++c) {
            float a0 = trans[lane*NK + 2*c], a1 = trans[lane*NK + 2*c + 1];
            // row mask: lane in 0..31, never SSTART(46)
            if (2*c   == SEND) a0 = NEGV;
            if (2*c+1 == SEND) a1 = NEGV;
            tpF[c] = pk2(a0, a1);
        }
        #pragma unroll
        for (int c = 0; c < 12; ++c) {
            const int p0 = 4*base6 + 2*c, p1 = p0 + 1;
            float a0 = trans[jh*NK + p0], a1 = trans[jh*NK + p1];
            if (jh == SSTART) { a0 = NEGV; a1 = NEGV; }
            if (p0 == SEND) a0 = NEGV;
            if (p1 == SEND) a1 = NEGV;
            tpH[c] = pk2(a0, a1);
        }
        vS[0][lane] = NEGV;                          // states 0..31 (none is START)
        if (lane < 16) vS[0][jh] = (jh == SSTART) ? 0.f : NEGV;
        __syncthreads();                              // table + init visible

        float fqA[2], fqB[2];
        fqA[0] = __ldg(f + lane);      fqA[1] = __ldg(f + NK + lane);
        fqB[0] = (lane < 16) ? __ldg(f + jh) : 0.f;
        fqB[1] = (lane < 16) ? __ldg(f + NK + jh) : 0.f;

        #pragma unroll 1
        for (int g = 0; g < NT/2; ++g) {
            #pragma unroll
            for (int u = 0; u < 2; ++u) {            // read buf u, write buf u^1
                const int t = g*2 + u;
                const float* vcur = vS[u];
                ulonglong2 vv[12];
                const ulonglong2* vp = (const ulonglong2*)vcur;
                #pragma unroll
                for (int c = 0; c < 12; ++c) vv[c] = vp[c];        // broadcast LDS.128
                const float featA = fqA[u], featB = fqB[u];
                if (t + 2 < NT) {
                    fqA[u] = __ldg(f + (t+2)*NK + lane);
                    if (lane < 16) fqB[u] = __ldg(f + (t+2)*NK + jh);
                }
                float bmF, bmH; int biF, biH;
                VIT_FULL(tpF, lane, bmF, biF);
                VIT_HALF(tpH, jh, base6, bmH, biH);
                // pair-merge state jh: upper half (prevs 24-47) wins only on strict >
                float om = __shfl_xor_sync(0xffffffffu, bmH, 16);
                int   oi = __shfl_xor_sync(0xffffffffu, biH, 16);
                vS[u^1][lane] = bmF + featA;          // emission AFTER max (reference)
                bp[t*NK + lane] = (unsigned char)biF;
                if (lane < 16) {
                    if (om > bmH) { bmH = om; biH = oi; }
                    vS[u^1][jh] = bmH + featB;
                    bp[t*NK + jh] = (unsigned char)biH;
                }
                __syncwarp();
            }
        }
        if (lane == 0) {
            float bm = -3.4e38f; int last = 0;
            #pragma unroll
            for (int p = 0; p < NK; ++p) {
                float te = trans[SEND*NK + p];
                if (p == SEND) te = NEGV;
                float y = vS[0][p] + te;
                if (y > bm) { bm = y; last = p; }
            }
            out[NB + b] = bm;
            float* po = out + 2*NB + (size_t)b * NT;
            int tag = last;
            #pragma unroll 1
            for (int t = NT - 1; t >= 0; --t) {      // natural bp layout
                po[t] = (float)tag;
                tag = bp[t*NK + tag];
            }
        }
    } else {
        // ============== FORWARD warp: unchanged from R13 =======================
        const int  ll  = (lane < 24) ? lane : (lane - 24);
        const bool act = (lane < 24);
        const int  j1  = ll, j2 = ll + 24;

        unsigned long long tpA[NK/2], tpB[NK/2];
        #pragma unroll
        for (int c = 0; c < NK/2; ++c) {
            const int p0 = 2*c, p1 = 2*c + 1;
            float a0 = trans[j1*NK+p0], a1 = trans[j1*NK+p1];
            float c0 = trans[j2*NK+p0], c1 = trans[j2*NK+p1];
            if (j1 == SSTART) { a0 = NEGV; a1 = NEGV; }
            if (j2 == SSTART) { c0 = NEGV; c1 = NEGV; }
            if (p0 == SEND)   { a0 = NEGV; c0 = NEGV; }
            if (p1 == SEND)   { a1 = NEGV; c1 = NEGV; }
            tpA[c] = pk2(ex2f(a0*L2E), ex2f(a1*L2E));   // exp-factored, masked -> 0
            tpB[c] = pk2(ex2f(c0*L2E), ex2f(c1*L2E));
        }
        if (act) { eS[0][j1] = (j1==SSTART)?1.f:0.f;  eS[0][j2] = (j2==SSTART)?1.f:0.f; }
        __syncthreads();                              // table + init visible

        float fq1[2], fq2[2];
        fq1[0] = __ldg(f + j1);      fq2[0] = __ldg(f + j2);
        fq1[1] = __ldg(f + NK + j1); fq2[1] = __ldg(f + NK + j2);

        float Csum = 0.f, A1 = 0.f, A2 = 0.f;
        #pragma unroll 1
        for (int g = 0; g < NT/2; ++g) {
            #pragma unroll
            for (int u = 0; u < 2; ++u) {
                const int t = g*2 + u;
                ulonglong2 vv[12];
                const ulonglong2* ep = (const ulonglong2*)eS[u];
                #pragma unroll
                for (int c = 0; c < 12; ++c) vv[c] = ep[c];        // broadcast LDS.128
                const float featv1 = fq1[u], featv2 = fq2[u];
                if (t + 2 < NT) { fq1[u] = __ldg(f + (t+2)*NK + j1);
                                  fq2[u] = __ldg(f + (t+2)*NK + j2); }
                unsigned long long a0=0ull, a1=0ull, a2=0ull, a3=0ull;
                #pragma unroll
                for (int c = 0; c < 12; ++c) {                     // packed f32x2 FFMA
                    a0 = ffma2(tpA[2*c  ], vv[c].x, a0);
                    a1 = ffma2(tpA[2*c+1], vv[c].y, a1);
                    a2 = ffma2(tpB[2*c  ], vv[c].x, a2);
                    a3 = ffma2(tpB[2*c+1], vv[c].y, a3);
                }
                float x0,x1,x2,x3,x4,x5,x6,x7;
                upk2(a0,x0,x1); upk2(a1,x2,x3); upk2(a2,x4,x5); upk2(a3,x6,x7);
                float s1 = (x0+x1)+(x2+x3);
                float s2 = (x4+x5)+(x6+x7);
                float raw1 = lg2f(s1) + featv1 * L2E;
                float raw2 = lg2f(s2) + featv2 * L2E;
                float d = __shfl_sync(0xffffffffu, raw1, 0);   // current raw[0] shift
                d = fminf(fmaxf(d, -200.f), 200.f);
                Csum += d;
                A1 = raw1 - d; A2 = raw2 - d;
                if (act) { eS[u^1][j1] = ex2f(A1); eS[u^1][j2] = ex2f(A2); }
                __syncwarp();
            }
        }
        if (act) { eS[1][j1] = A1; eS[1][j2] = A2; }
        __syncwarp();
        if (lane == 0) {
            float m = -3.4e38f;
            #pragma unroll
            for (int p = 0; p < NK; ++p) {
                float te = trans[SEND*NK + p];
                if (p == SEND) te = NEGV;
                m = fmaxf(m, eS[1][p] + te * L2E);
            }
            float s = 0.f;
            #pragma unroll
            for (int p = 0; p < NK; ++p) {
                float te = trans[SEND*NK + p];
                if (p == SEND) te = NEGV;
                s += ex2f(eS[1][p] + te * L2E - m);
            }
            out[b] = (m + lg2f(s) + Csum) * LN2F;
        }
    }
}

extern "C" void kernel_launch(void* const* d_in, const int* in_sizes, int n_in,
                              void* d_out, int out_size)
{
    const float* feats = (const float*)d_in[0];
    const float* trans = (const float*)d_in[1];
    float* out = (float*)d_out;
    cudaFuncSetAttribute(crf_kernel, cudaFuncAttributeMaxDynamicSharedMemorySize,
                         SMEM_BYTES);
    cudaFuncSetAttribute(crf_kernel, cudaFuncAttributePreferredSharedMemoryCarveout,
                         100);
    crf_kernel<<<NB/4, 256, SMEM_BYTES>>>(feats, trans, out);
}

// round 17
// speedup vs baseline: 1.8562x; 1.8562x over previous
#include <cuda_runtime.h>

#define NB 512
#define NT 1024
#define NK 48
#define SSTART 46
#define SEND 47
#define NEGV (-10000.0f)
#define L2E 1.4426950408889634f
#define LN2F 0.6931471805599453f

// per-batch slot: bp[NT*NK] u8 | v0[NK] | v1[NK] | e0[NK] | e1[NK] (each padded)
#define SLOT_V0 (NT*NK)
#define SLOT_V1 (SLOT_V0 + 256)
#define SLOT_E0 (SLOT_V1 + 256)
#define SLOT_E1 (SLOT_E0 + 256)
#define SLOT    (SLOT_E1 + 256)
#define TT_OFF  (4*SLOT)                     // masked trans table (shared by batches)
#define SMEM_BYTES (TT_OFF + NK*NK*4)        // ~209.9KB -> 1 CTA/SM

__device__ __forceinline__ float ex2f(float x){ float y; asm("ex2.approx.ftz.f32 %0, %1;":"=f"(y):"f"(x)); return y; }
__device__ __forceinline__ float lg2f(float x){ float y; asm("lg2.approx.f32 %0, %1;":"=f"(y):"f"(x)); return y; }
__device__ __forceinline__ unsigned long long ffma2(unsigned long long a, unsigned long long b, unsigned long long c){
    unsigned long long d; asm("fma.rn.f32x2 %0, %1, %2, %3;" : "=l"(d) : "l"(a), "l"(b), "l"(c)); return d;
}
__device__ __forceinline__ unsigned long long fadd2(unsigned long long a, unsigned long long b){
    unsigned long long d; asm("add.rn.f32x2 %0, %1, %2;" : "=l"(d) : "l"(a), "l"(b)); return d;
}
__device__ __forceinline__ unsigned long long pk2(float lo, float hi){
    unsigned long long d; asm("mov.b64 %0, {%1, %2};" : "=l"(d) : "f"(lo), "f"(hi)); return d;
}
__device__ __forceinline__ void upk2(unsigned long long v, float& lo, float& hi){
    asm("mov.b64 {%0, %1}, %2;" : "=f"(lo), "=f"(hi) : "l"(v));
}

// R13 coarse argmax, ONE change: the serial 12-link (bm,g4) predicated chain is
// split into TWO independent 6-link chains merged once. Each group max is still
// consumed immediately (no array liveness). Low half preferred on merge tie ->
// earliest group, then in-group first-equal recovery (bit-identical FADDs from
// smem) -> exact jnp.argmax first-max semantics; bm bit-identical.
#define VIT_STATE2(tp, jj, bm, bi) do { \
    float bmA = -3.4e38f, bmB = -3.4e38f; int gA = 0, gB = 6; \
    _Pragma("unroll") \
    for (int c=0;c<6;++c){ \
        unsigned long long y01=fadd2(vv[c].x,(tp)[2*c]); \
        unsigned long long y23=fadd2(vv[c].y,(tp)[2*c+1]); \
        float y0,y1,y2,y3; upk2(y01,y0,y1); upk2(y23,y2,y3); \
        float mg = fmaxf(fmaxf(y0,y1), fmaxf(y2,y3)); \
        if (mg > bmA) { bmA = mg; gA = c; } \
    } \
    _Pragma("unroll") \
    for (int c=6;c<12;++c){ \
        unsigned long long y01=fadd2(vv[c].x,(tp)[2*c]); \
        unsigned long long y23=fadd2(vv[c].y,(tp)[2*c+1]); \
        float y0,y1,y2,y3; upk2(y01,y0,y1); upk2(y23,y2,y3); \
        float mg = fmaxf(fmaxf(y0,y1), fmaxf(y2,y3)); \
        if (mg > bmB) { bmB = mg; gB = c; } \
    } \
    bm = bmA; int g4 = gA; \
    if (bmB > bm) { bm = bmB; g4 = gB; }    /* strict >: low half wins ties */ \
    const int p0 = 4*g4; \
    const float* trow = tT + (jj)*NK + p0; \
    float r0 = vcur[p0  ] + trow[0]; \
    float r1 = vcur[p0+1] + trow[1]; \
    float r2 = vcur[p0+2] + trow[2]; \
    bi = (r0==bm) ? p0 : (r1==bm) ? (p0+1) : (r2==bm) ? (p0+2) : (p0+3); \
} while(0)

__global__ __launch_bounds__(256, 1)
void crf_kernel(const float* __restrict__ feats,
                const float* __restrict__ trans,
                float* __restrict__ out)
{
    extern __shared__ char smc[];
    const int tid  = threadIdx.x;
    const int wid  = tid >> 5;
    const int lane = tid & 31;
    const int q    = wid & 3;                        // batch within CTA
    const bool isV = ((wid & 1) == (wid >> 2));      // SMSP gets 1 vit + 1 fwd
    const int b = blockIdx.x * 4 + q;
    char* sb = smc + q * SLOT;
    unsigned char* bp = (unsigned char*)sb;
    float* vS[2] = { (float*)(sb + SLOT_V0), (float*)(sb + SLOT_V1) };
    float* eS[2] = { (float*)(sb + SLOT_E0), (float*)(sb + SLOT_E1) };
    float* tT = (float*)(smc + TT_OFF);              // masked trans table (plain)
    const float* f = feats + (size_t)b * NT * NK;

    // cooperative fill of the masked trans table (one-time)
    for (int idx = tid; idx < NK*NK; idx += 256) {
        const int r = idx / NK, cpos = idx % NK;
        float tv = trans[idx];
        if (r == SSTART) tv = NEGV;                  // no transition into START row
        if (cpos == SEND) tv = NEGV;                 // no transition out of END col
        tT[idx] = tv;
    }

    const int  ll  = (lane < 24) ? lane : (lane - 24);
    const bool act = (lane < 24);
    const int  j1  = ll, j2 = ll + 24;               // two states per lane

    unsigned long long tpA[NK/2], tpB[NK/2];
    #pragma unroll
    for (int c = 0; c < NK/2; ++c) {
        const int p0 = 2*c, p1 = 2*c + 1;
        float a0 = trans[j1*NK+p0], a1 = trans[j1*NK+p1];
        float c0 = trans[j2*NK+p0], c1 = trans[j2*NK+p1];
        if (j1 == SSTART) { a0 = NEGV; a1 = NEGV; }
        if (j2 == SSTART) { c0 = NEGV; c1 = NEGV; }
        if (p0 == SEND)   { a0 = NEGV; c0 = NEGV; }
        if (p1 == SEND)   { a1 = NEGV; c1 = NEGV; }
        if (isV) { tpA[c] = pk2(a0, a1); tpB[c] = pk2(c0, c1); }     // plain (exact)
        else     { tpA[c] = pk2(ex2f(a0*L2E), ex2f(a1*L2E));          // exp-factored
                   tpB[c] = pk2(ex2f(c0*L2E), ex2f(c1*L2E)); }        // masked -> 0
    }
    if (act) {
        if (isV) { vS[0][j1] = (j1==SSTART)?0.f:NEGV;  vS[0][j2] = (j2==SSTART)?0.f:NEGV; }
        else     { eS[0][j1] = (j1==SSTART)?1.f:0.f;   eS[0][j2] = (j2==SSTART)?1.f:0.f; }
    }
    __syncthreads();                                  // table + init visible; then free-run

    float fq1[2], fq2[2];                            // 2-step feats prefetch
    fq1[0] = __ldg(f + j1);      fq2[0] = __ldg(f + j2);
    fq1[1] = __ldg(f + NK + j1); fq2[1] = __ldg(f + NK + j2);

    if (isV) {
        // ====== VITERBI: warp-private, double-buffered, ONE syncwarp/step ======
        #pragma unroll 1
        for (int g = 0; g < NT/2; ++g) {
            #pragma unroll
            for (int u = 0; u < 2; ++u) {            // read buf u, write buf u^1
                const int t = g*2 + u;
                const float* vcur = vS[u];
                ulonglong2 vv[12];
                const ulonglong2* vp = (const ulonglong2*)vcur;
                #pragma unroll
                for (int c = 0; c < 12; ++c) vv[c] = vp[c];        // broadcast LDS.128
                const float featv1 = fq1[u], featv2 = fq2[u];
                if (t + 2 < NT) { fq1[u] = __ldg(f + (t+2)*NK + j1);
                                  fq2[u] = __ldg(f + (t+2)*NK + j2); }
                float bm1, bm2; int bi1, bi2;
                VIT_STATE2(tpA, j1, bm1, bi1);       // plain float, exact max
                VIT_STATE2(tpB, j2, bm2, bi2);
                if (act) {
                    vS[u^1][j1] = bm1 + featv1;      // emission added AFTER max (ref)
                    vS[u^1][j2] = bm2 + featv2;
                    *(unsigned short*)(bp + t*NK + 2*ll) =
                        (unsigned short)(bi1 | (bi2 << 8));
                }
                __syncwarp();
            }
        }
        if (lane == 0) {
            float bm = -3.4e38f; int last = 0;
            #pragma unroll
            for (int p = 0; p < NK; ++p) {
                float te = trans[SEND*NK + p];
                if (p == SEND) te = NEGV;
                float y = vS[0][p] + te;
                if (y > bm) { bm = y; last = p; }
            }
            out[NB + b] = bm;
            float* po = out + 2*NB + (size_t)b * NT;
            int tag = last;
            #pragma unroll 1
            for (int t = NT - 1; t >= 0; --t) {
                po[t] = (float)tag;
                int off = (tag < 24) ? (2*tag) : (2*tag - 47);
                tag = bp[t*NK + off];
            }
        }
    } else {
        // ====== FORWARD: warp-private, double-buffered, ONE syncwarp/step ======
        float Csum = 0.f, A1 = 0.f, A2 = 0.f;
        #pragma unroll 1
        for (int g = 0; g < NT/2; ++g) {
            #pragma unroll
            for (int u = 0; u < 2; ++u) {
                const int t = g*2 + u;
                ulonglong2 vv[12];
                const ulonglong2* ep = (const ulonglong2*)eS[u];
                #pragma unroll
                for (int c = 0; c < 12; ++c) vv[c] = ep[c];        // broadcast LDS.128
                const float featv1 = fq1[u], featv2 = fq2[u];
                if (t + 2 < NT) { fq1[u] = __ldg(f + (t+2)*NK + j1);
                                  fq2[u] = __ldg(f + (t+2)*NK + j2); }
                unsigned long long a0=0ull, a1=0ull, a2=0ull, a3=0ull;
                #pragma unroll
                for (int c = 0; c < 12; ++c) {                     // packed f32x2 FFMA
                    a0 = ffma2(tpA[2*c  ], vv[c].x, a0);
                    a1 = ffma2(tpA[2*c+1], vv[c].y, a1);
                    a2 = ffma2(tpB[2*c  ], vv[c].x, a2);
                    a3 = ffma2(tpB[2*c+1], vv[c].y, a3);
                }
                float x0,x1,x2,x3,x4,x5,x6,x7;
                upk2(a0,x0,x1); upk2(a1,x2,x3); upk2(a2,x4,x5); upk2(a3,x6,x7);
                float s1 = (x0+x1)+(x2+x3);
                float s2 = (x4+x5)+(x6+x7);
                float raw1 = lg2f(s1) + featv1 * L2E;
                float raw2 = lg2f(s2) + featv2 * L2E;
                float d = __shfl_sync(0xffffffffu, raw1, 0);   // current raw[0] shift
                d = fminf(fmaxf(d, -200.f), 200.f);
                Csum += d;
                A1 = raw1 - d; A2 = raw2 - d;
                if (act) { eS[u^1][j1] = ex2f(A1); eS[u^1][j2] = ex2f(A2); }
                __syncwarp();
            }
        }
        if (act) { eS[1][j1] = A1; eS[1][j2] = A2; }
        __syncwarp();
        if (lane == 0) {
            float m = -3.4e38f;
            #pragma unroll
            for (int p = 0; p < NK; ++p) {
                float te = trans[SEND*NK + p];
                if (p == SEND) te = NEGV;
                m = fmaxf(m, eS[1][p] + te * L2E);
            }
            float s = 0.f;
            #pragma unroll
            for (int p = 0; p < NK; ++p) {
                float te = trans[SEND*NK + p];
                if (p == SEND) te = NEGV;
                s += ex2f(eS[1][p] + te * L2E - m);
            }
            out[b] = (m + lg2f(s) + Csum) * LN2F;
        }
    }
}

extern "C" void kernel_launch(void* const* d_in, const int* in_sizes, int n_in,
                              void* d_out, int out_size)
{
    const float* feats = (const float*)d_in[0];
    const float* trans = (const float*)d_in[1];
    float* out = (float*)d_out;
    cudaFuncSetAttribute(crf_kernel, cudaFuncAttributeMaxDynamicSharedMemorySize,
                         SMEM_BYTES);
    cudaFuncSetAttribute(crf_kernel, cudaFuncAttributePreferredSharedMemoryCarveout,
                         100);
    crf_kernel<<<NB/4, 256, SMEM_BYTES>>>(feats, trans, out);
}